// round 4
// baseline (speedup 1.0000x reference)
#include <cuda_runtime.h>

#define NN 100000
#define F1 128
#define F2 64
#define F3 40

// ---------------- scratch (device globals; no allocation allowed) ----------
__device__ __align__(16) int   g_deg[NN];
__device__ __align__(16) float g_dis[NN];
__device__ __align__(16) float g_xws[NN * F2];   // (x@W1) * dis[row]
__device__ __align__(16) float g_acc1[NN * F2];  // scatter accumulator layer 1
__device__ __align__(16) float g_h[NN * F2];     // relu output of layer 1
__device__ __align__(16) float g_hw[NN * F3];    // (h@W2) * dis[row]
__device__ __align__(16) float g_acc2[NN * F3];  // scatter accumulator layer 2
__device__ int g_is64;                           // edge_index dtype flag

// ---------------- edge index fetch (dtype-agnostic) ------------------------
__device__ __forceinline__ int edge_idx(const void* ei, long long E,
                                        long long e, int which) {
    int v;
    if (g_is64) v = (int)((const long long*)ei)[(long long)which * E + e];
    else        v = ((const int*)ei)[(long long)which * E + e];
    return v;
}

// ---------------- dtype probe: int64 indices < 2^31 have zero high words ---
__global__ void k_detect(const int* __restrict__ ei) {
    if (threadIdx.x == 0 && blockIdx.x == 0) {
        int ones = 0;
        for (int i = 0; i < 256; i++) ones |= ei[2 * i + 1];
        g_is64 = (ones == 0) ? 1 : 0;
    }
}

// ---------------- zero scratch (graph memset nodes can't touch __device__ globals)
__global__ void k_zero() {
    int i = blockIdx.x * blockDim.x + threadIdx.x;
    if (i < NN) g_deg[i] = 0;
    float4 z = make_float4(0.f, 0.f, 0.f, 0.f);
    float4* a1 = (float4*)g_acc1;
    for (int j = i; j < NN * (F2 / 4); j += gridDim.x * blockDim.x) a1[j] = z;
    float4* a2 = (float4*)g_acc2;
    for (int j = i; j < NN * (F3 / 4); j += gridDim.x * blockDim.x) a2[j] = z;
}

// ---------------- degree ---------------------------------------------------
__global__ void k_deg(const void* __restrict__ ei, int E) {
    int i = blockIdx.x * blockDim.x + threadIdx.x;
    if (i >= E) return;
    int d = edge_idx(ei, E, i, 1);
    if ((unsigned)d < NN) atomicAdd(&g_deg[d], 1);
}

__global__ void k_dis() {
    int i = blockIdx.x * blockDim.x + threadIdx.x;
    if (i < NN) g_dis[i] = rsqrtf((float)(g_deg[i] + 1));  // +1 self loop
}

// ---------------- GEMM1: xws = (x @ W1) * dis ------------------------------
// block = 256 threads = 8 warps; each warp computes 4 rows; 32 rows/block.
__global__ void k_gemm1(const float* __restrict__ X, const float* __restrict__ W) {
    __shared__ float2 sW[F1 * 32];  // sW[k*32+c] = {W[k][c], W[k][c+32]}
    int tid = threadIdx.x;
    for (int idx = tid; idx < F1 * 32; idx += blockDim.x) {
        int k = idx >> 5, c = idx & 31;
        sW[idx] = make_float2(W[k * F2 + c], W[k * F2 + c + 32]);
    }
    __syncthreads();

    int lane = tid & 31, warp = tid >> 5;
    int rbase = blockIdx.x * 32 + warp * 4;

    float xr[4][4];
    #pragma unroll
    for (int j = 0; j < 4; j++) {
        int r = min(rbase + j, NN - 1);
        const float* xp = X + (size_t)r * F1;
        #pragma unroll
        for (int t = 0; t < 4; t++) xr[j][t] = xp[lane + 32 * t];
    }

    float a0[4] = {0.f, 0.f, 0.f, 0.f}, a1[4] = {0.f, 0.f, 0.f, 0.f};
    #pragma unroll
    for (int k = 0; k < F1; k++) {
        float2 w = sW[k * 32 + lane];
        #pragma unroll
        for (int j = 0; j < 4; j++) {
            float xk = __shfl_sync(0xffffffffu, xr[j][k >> 5], k & 31);
            a0[j] = fmaf(xk, w.x, a0[j]);
            a1[j] = fmaf(xk, w.y, a1[j]);
        }
    }

    #pragma unroll
    for (int j = 0; j < 4; j++) {
        int r = rbase + j;
        if (r < NN) {
            float d = g_dis[r];
            g_xws[(size_t)r * F2 + lane]      = a0[j] * d;
            g_xws[(size_t)r * F2 + lane + 32] = a1[j] * d;
        }
    }
}

// ---------------- scatter-add (gather row of src, vector atomic into dst) --
// Layer 1: F=64 -> 16 float4 chunks, 16 lanes/edge, 2 edges/warp
__global__ void k_scatter1(const void* __restrict__ ei, int E) {
    int lane = threadIdx.x & 31;
    int gi = lane >> 4;          // group in warp (0..1)
    int c  = lane & 15;          // chunk
    long long wid = (long long)blockIdx.x * (blockDim.x >> 5) + (threadIdx.x >> 5);
    long long e = wid * 2 + gi;
    if (e >= E) return;
    int s = edge_idx(ei, E, e, 0);
    int d = edge_idx(ei, E, e, 1);
    if ((unsigned)s >= NN || (unsigned)d >= NN) return;
    const float4* ip = (const float4*)(g_xws + (size_t)s * F2);
    float4 v = ip[c];
    atomicAdd((float4*)(g_acc1 + (size_t)d * F2 + c * 4), v);
}

// Layer 2: F=40 -> 10 float4 chunks, 10 lanes/edge, 3 edges/warp (lanes 30,31 idle)
__global__ void k_scatter2(const void* __restrict__ ei, int E) {
    int lane = threadIdx.x & 31;
    int gi = lane / 10;
    int c  = lane % 10;
    if (gi >= 3) return;
    long long wid = (long long)blockIdx.x * (blockDim.x >> 5) + (threadIdx.x >> 5);
    long long e = wid * 3 + gi;
    if (e >= E) return;
    int s = edge_idx(ei, E, e, 0);
    int d = edge_idx(ei, E, e, 1);
    if ((unsigned)s >= NN || (unsigned)d >= NN) return;
    const float4* ip = (const float4*)(g_hw + (size_t)s * F3);
    float4 v = ip[c];
    atomicAdd((float4*)(g_acc2 + (size_t)d * F3 + c * 4), v);
}

// ---------------- finalize layer 1: h = relu(dis*(acc+xws)+b1) -------------
__global__ void k_fin1(const float* __restrict__ b1) {
    size_t i = (size_t)blockIdx.x * blockDim.x + threadIdx.x;
    if (i >= (size_t)NN * F2) return;
    int r = (int)(i >> 6);
    int c = (int)(i & 63);
    float v = g_dis[r] * (g_acc1[i] + g_xws[i]) + b1[c];
    g_h[i] = v > 0.f ? v : 0.f;
}

// ---------------- GEMM2: hw = (h @ W2) * dis -------------------------------
__global__ void k_gemm2(const float* __restrict__ W) {
    __shared__ float sW[F2 * F3];  // [k][c] row-major 64x40
    int tid = threadIdx.x;
    for (int idx = tid; idx < F2 * F3; idx += blockDim.x) sW[idx] = W[idx];
    __syncthreads();

    int lane = tid & 31, warp = tid >> 5;
    int rbase = blockIdx.x * 32 + warp * 4;

    float xr[4][2];
    #pragma unroll
    for (int j = 0; j < 4; j++) {
        int r = min(rbase + j, NN - 1);
        const float* xp = g_h + (size_t)r * F2;
        xr[j][0] = xp[lane];
        xr[j][1] = xp[lane + 32];
    }

    float a0[4] = {0.f, 0.f, 0.f, 0.f}, a1[4] = {0.f, 0.f, 0.f, 0.f};
    int c2 = 32 + (lane & 7);  // clamped 2nd column index (valid mem for all lanes)
    #pragma unroll
    for (int k = 0; k < F2; k++) {
        float w0 = sW[k * F3 + lane];
        float w1 = sW[k * F3 + c2];
        #pragma unroll
        for (int j = 0; j < 4; j++) {
            float xk = __shfl_sync(0xffffffffu, xr[j][k >> 5], k & 31);
            a0[j] = fmaf(xk, w0, a0[j]);
            a1[j] = fmaf(xk, w1, a1[j]);
        }
    }

    #pragma unroll
    for (int j = 0; j < 4; j++) {
        int r = rbase + j;
        if (r < NN) {
            float d = g_dis[r];
            g_hw[(size_t)r * F3 + lane] = a0[j] * d;
            if (lane < 8) g_hw[(size_t)r * F3 + c2] = a1[j] * d;
        }
    }
}

// ---------------- finalize layer 2 + log-softmax (warp per row) ------------
__global__ void k_fin2(const float* __restrict__ b2, float* __restrict__ out) {
    int lane = threadIdx.x & 31;
    int r = blockIdx.x * (blockDim.x >> 5) + (threadIdx.x >> 5);
    if (r >= NN) return;
    float dd = g_dis[r];
    size_t base = (size_t)r * F3;
    int c1 = 32 + (lane & 7);
    bool has1 = lane < 8;

    float z0 = dd * (g_acc2[base + lane] + g_hw[base + lane]) + b2[lane];
    float z1 = dd * (g_acc2[base + c1] + g_hw[base + c1]) + b2[c1];

    float m = fmaxf(z0, has1 ? z1 : -3.4e38f);
    #pragma unroll
    for (int o = 16; o; o >>= 1) m = fmaxf(m, __shfl_xor_sync(0xffffffffu, m, o));
    float s = expf(z0 - m) + (has1 ? expf(z1 - m) : 0.f);
    #pragma unroll
    for (int o = 16; o; o >>= 1) s += __shfl_xor_sync(0xffffffffu, s, o);
    float lse = m + logf(s);

    out[base + lane] = z0 - lse;
    if (has1) out[base + c1] = z1 - lse;
}

// ---------------- launcher -------------------------------------------------
extern "C" void kernel_launch(void* const* d_in, const int* in_sizes, int n_in,
                              void* d_out, int out_size) {
    const float* x   = (const float*)d_in[0];
    const void*  ei  = d_in[1];
    const float* W1  = (const float*)d_in[2];
    const float* b1  = (const float*)d_in[3];
    const float* W2  = (const float*)d_in[4];
    const float* b2  = (const float*)d_in[5];
    float* out = (float*)d_out;

    int E = in_sizes[1] / 2;

    k_detect<<<1, 32>>>((const int*)ei);
    k_zero<<<2048, 256>>>();

    k_deg<<<(E + 255) / 256, 256>>>(ei, E);
    k_dis<<<(NN + 255) / 256, 256>>>();

    k_gemm1<<<(NN + 31) / 32, 256>>>(x, W1);

    {   // 2 edges per warp
        long long nwarp = ((long long)E + 1) / 2;
        int blocks = (int)((nwarp * 32 + 255) / 256);
        k_scatter1<<<blocks, 256>>>(ei, E);
    }

    k_fin1<<<(NN * F2 + 255) / 256, 256>>>(b1);

    k_gemm2<<<(NN + 31) / 32, 256>>>(W2);

    {   // 3 edges per warp
        long long nwarp = ((long long)E + 2) / 3;
        int blocks = (int)((nwarp * 32 + 255) / 256);
        k_scatter2<<<blocks, 256>>>(ei, E);
    }

    k_fin2<<<(NN + 7) / 8, 256>>>(b2, out);
}

// round 5
// speedup vs baseline: 1.3069x; 1.3069x over previous
#include <cuda_runtime.h>

#define NN 100000
#define F1 128
#define F2 64
#define F3 40
#define EMAX 1700000
#define NB 391  // ceil(NN/256)

// ---------------- scratch (device globals; no allocation allowed) ----------
__device__ int   g_deg[NN];
__device__ float g_dis[NN];
__device__ int   g_off[NN + 1];   // CSR row offsets (by dst)
__device__ int   g_cur[NN];       // fill cursors
__device__ int   g_bsum[512];     // scan block sums
__device__ int   g_csr[EMAX];     // src indices grouped by dst
__device__ __align__(16) float2 g_xws[NN * 32];  // (x@W1)*dis, paired cols {c, c+32}
__device__ __align__(16) float2 g_h[NN * 32];    // relu out, paired cols {c, c+32}
__device__ __align__(16) float  g_hwf[NN * F3];  // (h@W2)*dis, natural layout
__device__ int g_is64;

// ---------------- edge index fetch (dtype-agnostic) ------------------------
__device__ __forceinline__ int edge_idx(const void* ei, long long E,
                                        long long e, int which) {
    if (g_is64) return (int)((const long long*)ei)[(long long)which * E + e];
    return ((const int*)ei)[(long long)which * E + e];
}

__global__ void k_detect(const int* __restrict__ ei) {
    if (threadIdx.x == 0 && blockIdx.x == 0) {
        int ones = 0;
        for (int i = 0; i < 256; i++) ones |= ei[2 * i + 1];
        g_is64 = (ones == 0) ? 1 : 0;
    }
}

__global__ void k_zerodeg() {
    int i = blockIdx.x * blockDim.x + threadIdx.x;
    if (i < NN) g_deg[i] = 0;
}

__global__ void k_deg(const void* __restrict__ ei, int E) {
    int i = blockIdx.x * blockDim.x + threadIdx.x;
    if (i >= E) return;
    int d = edge_idx(ei, E, i, 1);
    if ((unsigned)d < NN) atomicAdd(&g_deg[d], 1);
}

__global__ void k_dis() {
    int i = blockIdx.x * blockDim.x + threadIdx.x;
    if (i < NN) g_dis[i] = rsqrtf((float)(g_deg[i] + 1));  // +1 self loop
}

// ---------------- CSR build: 3-step scan + fill ----------------------------
__global__ void k_scan1() {
    __shared__ int wsum[8];
    int i = blockIdx.x * 256 + threadIdx.x;
    int lane = threadIdx.x & 31, w = threadIdx.x >> 5;
    int incl = (i < NN) ? g_deg[i] : 0;
    #pragma unroll
    for (int o = 1; o < 32; o <<= 1) {
        int t = __shfl_up_sync(0xffffffffu, incl, o);
        if (lane >= o) incl += t;
    }
    if (lane == 31) wsum[w] = incl;
    __syncthreads();
    if (w == 0) {
        int s = (lane < 8) ? wsum[lane] : 0;
        #pragma unroll
        for (int o = 1; o < 8; o <<= 1) {
            int t = __shfl_up_sync(0xffffffffu, s, o);
            if (lane >= o) s += t;
        }
        if (lane < 8) wsum[lane] = s;
    }
    __syncthreads();
    if (w > 0) incl += wsum[w - 1];
    if (i < NN) g_off[i + 1] = incl;
    if (threadIdx.x == 255) g_bsum[blockIdx.x] = incl;
}

__global__ void k_scan2() {
    __shared__ int s[512];
    int t = threadIdx.x;
    s[t] = (t < NB) ? g_bsum[t] : 0;
    __syncthreads();
    for (int o = 1; o < 512; o <<= 1) {
        int v = (t >= o) ? s[t - o] : 0;
        __syncthreads();
        s[t] += v;
        __syncthreads();
    }
    if (t < NB) g_bsum[t] = (t > 0) ? s[t - 1] : 0;  // exclusive
}

__global__ void k_scan3() {
    int j = blockIdx.x * blockDim.x + threadIdx.x;
    if (j > NN) return;
    int v = (j == 0) ? 0 : g_off[j] + g_bsum[(j - 1) >> 8];
    g_off[j] = v;
    if (j < NN) g_cur[j] = v;
}

__global__ void k_fill(const void* __restrict__ ei, int E) {
    int e = blockIdx.x * blockDim.x + threadIdx.x;
    if (e >= E) return;
    int s = edge_idx(ei, E, e, 0);
    int d = edge_idx(ei, E, e, 1);
    if ((unsigned)s >= NN || (unsigned)d >= NN) return;
    int pos = atomicAdd(&g_cur[d], 1);
    if (pos < EMAX) g_csr[pos] = s;
}

// ---------------- GEMM1: xws = (x @ W1) * dis, paired layout ---------------
__global__ void k_gemm1(const float* __restrict__ X, const float* __restrict__ W) {
    __shared__ float2 sW[F1 * 32];  // sW[k*32+c] = {W[k][c], W[k][c+32]}
    int tid = threadIdx.x;
    for (int idx = tid; idx < F1 * 32; idx += blockDim.x) {
        int k = idx >> 5, c = idx & 31;
        sW[idx] = make_float2(W[k * F2 + c], W[k * F2 + c + 32]);
    }
    __syncthreads();

    int lane = tid & 31, warp = tid >> 5;
    int rbase = blockIdx.x * 32 + warp * 4;

    float xr[4][4];
    #pragma unroll
    for (int j = 0; j < 4; j++) {
        int r = min(rbase + j, NN - 1);
        const float* xp = X + (size_t)r * F1;
        #pragma unroll
        for (int t = 0; t < 4; t++) xr[j][t] = xp[lane + 32 * t];
    }

    float a0[4] = {0.f, 0.f, 0.f, 0.f}, a1[4] = {0.f, 0.f, 0.f, 0.f};
    #pragma unroll
    for (int k = 0; k < F1; k++) {
        float2 w = sW[k * 32 + lane];
        #pragma unroll
        for (int j = 0; j < 4; j++) {
            float xk = __shfl_sync(0xffffffffu, xr[j][k >> 5], k & 31);
            a0[j] = fmaf(xk, w.x, a0[j]);
            a1[j] = fmaf(xk, w.y, a1[j]);
        }
    }

    #pragma unroll
    for (int j = 0; j < 4; j++) {
        int r = rbase + j;
        if (r < NN) {
            float d = g_dis[r];
            g_xws[r * 32 + lane] = make_float2(a0[j] * d, a1[j] * d);
        }
    }
}

// ---------------- agg1: segment-reduce + self-loop + bias + relu -----------
__global__ void k_agg1(const float* __restrict__ b1) {
    int lane = threadIdx.x & 31;
    int n = blockIdx.x * 8 + (threadIdx.x >> 5);
    if (n >= NN) return;
    int beg = g_off[n], end = g_off[n + 1];

    float2 accA = g_xws[n * 32 + lane];  // self-loop term
    float2 accB = make_float2(0.f, 0.f);

    for (int base = beg; base < end; base += 32) {
        int cnt = min(32, end - base);
        int sl = (lane < cnt) ? g_csr[base + lane] : 0;
        int k = 0;
        for (; k + 1 < cnt; k += 2) {
            int s0 = __shfl_sync(0xffffffffu, sl, k);
            int s1 = __shfl_sync(0xffffffffu, sl, k + 1);
            float2 v0 = g_xws[s0 * 32 + lane];
            float2 v1 = g_xws[s1 * 32 + lane];
            accA.x += v0.x; accA.y += v0.y;
            accB.x += v1.x; accB.y += v1.y;
        }
        if (k < cnt) {
            int s0 = __shfl_sync(0xffffffffu, sl, k);
            float2 v = g_xws[s0 * 32 + lane];
            accA.x += v.x; accA.y += v.y;
        }
    }
    float d = g_dis[n];
    float hx = d * (accA.x + accB.x) + b1[lane];
    float hy = d * (accA.y + accB.y) + b1[lane + 32];
    g_h[n * 32 + lane] = make_float2(fmaxf(hx, 0.f), fmaxf(hy, 0.f));
}

// ---------------- GEMM2: hw = (h @ W2) * dis -------------------------------
__global__ void k_gemm2(const float* __restrict__ W) {
    __shared__ float sW[F2 * F3];  // [k][c] row-major 64x40
    int tid = threadIdx.x;
    for (int idx = tid; idx < F2 * F3; idx += blockDim.x) sW[idx] = W[idx];
    __syncthreads();

    int lane = tid & 31, warp = tid >> 5;
    int rbase = blockIdx.x * 32 + warp * 4;

    float xr[4][2];
    #pragma unroll
    for (int j = 0; j < 4; j++) {
        int r = min(rbase + j, NN - 1);
        float2 p = g_h[r * 32 + lane];
        xr[j][0] = p.x;
        xr[j][1] = p.y;
    }

    float a0[4] = {0.f, 0.f, 0.f, 0.f}, a1[4] = {0.f, 0.f, 0.f, 0.f};
    int c2 = 32 + (lane & 7);
    #pragma unroll
    for (int k = 0; k < F2; k++) {
        float w0 = sW[k * F3 + lane];
        float w1 = sW[k * F3 + c2];
        #pragma unroll
        for (int j = 0; j < 4; j++) {
            float xk = __shfl_sync(0xffffffffu, xr[j][k >> 5], k & 31);
            a0[j] = fmaf(xk, w0, a0[j]);
            a1[j] = fmaf(xk, w1, a1[j]);
        }
    }

    #pragma unroll
    for (int j = 0; j < 4; j++) {
        int r = rbase + j;
        if (r < NN) {
            float d = g_dis[r];
            g_hwf[(size_t)r * F3 + lane] = a0[j] * d;
            if (lane < 8) g_hwf[(size_t)r * F3 + c2] = a1[j] * d;
        }
    }
}

// ---------------- agg2: reduce + self + bias + log-softmax -----------------
__global__ void k_agg2(const float* __restrict__ b2, float* __restrict__ out) {
    int lane = threadIdx.x & 31;
    int n = blockIdx.x * 8 + (threadIdx.x >> 5);
    if (n >= NN) return;
    bool act = lane < 20;
    const float2* hw2 = (const float2*)g_hwf;  // 20 float2 per row
    int beg = g_off[n], end = g_off[n + 1];

    float2 accA = act ? hw2[n * 20 + lane] : make_float2(0.f, 0.f);  // self-loop
    float2 accB = make_float2(0.f, 0.f);

    for (int base = beg; base < end; base += 32) {
        int cnt = min(32, end - base);
        int sl = (lane < cnt) ? g_csr[base + lane] : 0;
        int k = 0;
        for (; k + 1 < cnt; k += 2) {
            int s0 = __shfl_sync(0xffffffffu, sl, k);
            int s1 = __shfl_sync(0xffffffffu, sl, k + 1);
            if (act) {
                float2 v0 = hw2[s0 * 20 + lane];
                float2 v1 = hw2[s1 * 20 + lane];
                accA.x += v0.x; accA.y += v0.y;
                accB.x += v1.x; accB.y += v1.y;
            }
        }
        if (k < cnt) {
            int s0 = __shfl_sync(0xffffffffu, sl, k);
            if (act) {
                float2 v = hw2[s0 * 20 + lane];
                accA.x += v.x; accA.y += v.y;
            }
        }
    }

    float d = g_dis[n];
    float zx = act ? d * (accA.x + accB.x) + b2[2 * lane]     : -3.4e38f;
    float zy = act ? d * (accA.y + accB.y) + b2[2 * lane + 1] : -3.4e38f;

    float m = fmaxf(zx, zy);
    #pragma unroll
    for (int o = 16; o; o >>= 1) m = fmaxf(m, __shfl_xor_sync(0xffffffffu, m, o));
    float s = act ? (expf(zx - m) + expf(zy - m)) : 0.f;
    #pragma unroll
    for (int o = 16; o; o >>= 1) s += __shfl_xor_sync(0xffffffffu, s, o);
    float lse = m + logf(s);

    if (act) {
        out[(size_t)n * F3 + 2 * lane]     = zx - lse;
        out[(size_t)n * F3 + 2 * lane + 1] = zy - lse;
    }
}

// ---------------- launcher -------------------------------------------------
extern "C" void kernel_launch(void* const* d_in, const int* in_sizes, int n_in,
                              void* d_out, int out_size) {
    const float* x  = (const float*)d_in[0];
    const void*  ei = d_in[1];
    const float* W1 = (const float*)d_in[2];
    const float* b1 = (const float*)d_in[3];
    const float* W2 = (const float*)d_in[4];
    const float* b2 = (const float*)d_in[5];
    float* out = (float*)d_out;

    int E = in_sizes[1] / 2;
    int eb = (E + 255) / 256;

    k_detect<<<1, 32>>>((const int*)ei);
    k_zerodeg<<<NB, 256>>>();
    k_deg<<<eb, 256>>>(ei, E);
    k_dis<<<NB, 256>>>();
    k_scan1<<<NB, 256>>>();
    k_scan2<<<1, 512>>>();
    k_scan3<<<(NN + 256) / 256, 256>>>();
    k_fill<<<eb, 256>>>(ei, E);

    k_gemm1<<<(NN + 31) / 32, 256>>>(x, W1);
    k_agg1<<<(NN + 7) / 8, 256>>>(b1);
    k_gemm2<<<(NN + 31) / 32, 256>>>(W2);
    k_agg2<<<(NN + 7) / 8, 256>>>(b2, out);
}

// round 6
// speedup vs baseline: 1.6240x; 1.2427x over previous
#include <cuda_runtime.h>

#define NN 100000
#define F1 128
#define F2 64
#define F3 40
#define EMAX 1700000
#define NB 391  // ceil(NN/256)

// ---------------- scratch ---------------------------------------------------
__device__ int   g_deg[NN];
__device__ float g_dis[NN];
__device__ int   g_off[NN + 1];
__device__ int   g_cur[NN];
__device__ int   g_bsum[512];
__device__ int   g_csr[EMAX];
__device__ __align__(16) float g_xws[NN * F2];  // (x@W1)*dis, natural [r][64]
__device__ __align__(16) float g_h[NN * F2];    // relu out, natural [r][64]
__device__ __align__(16) float g_hwf[NN * F3];  // (h@W2)*dis, natural [r][40]
__device__ int g_is64;

// ---------------- edge index fetch (dtype-agnostic) -------------------------
__device__ __forceinline__ int edge_idx(const void* ei, long long E,
                                        long long e, int which) {
    if (g_is64) return (int)((const long long*)ei)[(long long)which * E + e];
    return ((const int*)ei)[(long long)which * E + e];
}

// ---------------- init: dtype probe + zero degree ---------------------------
__global__ void k_init(const int* __restrict__ ei) {
    int i = blockIdx.x * blockDim.x + threadIdx.x;
    if (i < NN) g_deg[i] = 0;
    if (i == 0) {
        int ones = 0;
        for (int j = 0; j < 256; j++) ones |= ei[2 * j + 1];
        g_is64 = (ones == 0) ? 1 : 0;
    }
}

__global__ void k_deg(const void* __restrict__ ei, int E) {
    int i = blockIdx.x * blockDim.x + threadIdx.x;
    if (i >= E) return;
    int d = edge_idx(ei, E, i, 1);
    if ((unsigned)d < NN) atomicAdd(&g_deg[d], 1);
}

// ---------------- dis + scan step 1 -----------------------------------------
__global__ void k_dis_scan1() {
    __shared__ int wsum[8];
    int i = blockIdx.x * 256 + threadIdx.x;
    int lane = threadIdx.x & 31, w = threadIdx.x >> 5;
    int deg = (i < NN) ? g_deg[i] : 0;
    if (i < NN) g_dis[i] = rsqrtf((float)(deg + 1));
    int incl = deg;
    #pragma unroll
    for (int o = 1; o < 32; o <<= 1) {
        int t = __shfl_up_sync(0xffffffffu, incl, o);
        if (lane >= o) incl += t;
    }
    if (lane == 31) wsum[w] = incl;
    __syncthreads();
    if (w == 0) {
        int s = (lane < 8) ? wsum[lane] : 0;
        #pragma unroll
        for (int o = 1; o < 8; o <<= 1) {
            int t = __shfl_up_sync(0xffffffffu, s, o);
            if (lane >= o) s += t;
        }
        if (lane < 8) wsum[lane] = s;
    }
    __syncthreads();
    if (w > 0) incl += wsum[w - 1];
    if (i < NN) g_off[i + 1] = incl;
    if (threadIdx.x == 255) g_bsum[blockIdx.x] = incl;
}

__global__ void k_scan2() {
    __shared__ int s[512];
    int t = threadIdx.x;
    s[t] = (t < NB) ? g_bsum[t] : 0;
    __syncthreads();
    for (int o = 1; o < 512; o <<= 1) {
        int v = (t >= o) ? s[t - o] : 0;
        __syncthreads();
        s[t] += v;
        __syncthreads();
    }
    if (t < NB) g_bsum[t] = (t > 0) ? s[t - 1] : 0;
}

__global__ void k_scan3() {
    int j = blockIdx.x * blockDim.x + threadIdx.x;
    if (j > NN) return;
    int v = (j == 0) ? 0 : g_off[j] + g_bsum[(j - 1) >> 8];
    g_off[j] = v;
    if (j < NN) g_cur[j] = v;
}

__global__ void k_fill(const void* __restrict__ ei, int E) {
    int e = blockIdx.x * blockDim.x + threadIdx.x;
    if (e >= E) return;
    int s = edge_idx(ei, E, e, 0);
    int d = edge_idx(ei, E, e, 1);
    if ((unsigned)s >= NN || (unsigned)d >= NN) return;
    int pos = atomicAdd(&g_cur[d], 1);
    if (pos < EMAX) g_csr[pos] = s;
}

// ---------------- GEMM1: smem-tiled 64x64, 4x4 micro-tile -------------------
__global__ void k_gemm1(const float* __restrict__ X, const float* __restrict__ W) {
    __shared__ float Xs[16][68];  // [k][row], padded
    __shared__ float Ws[16][64];  // [k][col]
    int tid = threadIdx.x;
    int tx = tid & 15, ty = tid >> 4;
    int rbase = blockIdx.x * 64;

    float c[4][4] = {};

    for (int kc = 0; kc < F1; kc += 16) {
        {   // X tile: float4 X[rbase + tid/4][kc + (tid&3)*4], store transposed
            int row = tid >> 2;
            int kk = (tid & 3) * 4;
            int rr = min(rbase + row, NN - 1);
            float4 v = *(const float4*)(X + (size_t)rr * F1 + kc + kk);
            Xs[kk + 0][row] = v.x;
            Xs[kk + 1][row] = v.y;
            Xs[kk + 2][row] = v.z;
            Xs[kk + 3][row] = v.w;
        }
        {   // W tile: float4 W[kc + ty][tx*4]
            float4 v = *(const float4*)(W + (size_t)(kc + ty) * F2 + tx * 4);
            *(float4*)&Ws[ty][tx * 4] = v;
        }
        __syncthreads();
        #pragma unroll
        for (int k = 0; k < 16; k++) {
            float4 a = *(float4*)&Xs[k][ty * 4];
            float4 b = *(float4*)&Ws[k][tx * 4];
            c[0][0] = fmaf(a.x, b.x, c[0][0]); c[0][1] = fmaf(a.x, b.y, c[0][1]);
            c[0][2] = fmaf(a.x, b.z, c[0][2]); c[0][3] = fmaf(a.x, b.w, c[0][3]);
            c[1][0] = fmaf(a.y, b.x, c[1][0]); c[1][1] = fmaf(a.y, b.y, c[1][1]);
            c[1][2] = fmaf(a.y, b.z, c[1][2]); c[1][3] = fmaf(a.y, b.w, c[1][3]);
            c[2][0] = fmaf(a.z, b.x, c[2][0]); c[2][1] = fmaf(a.z, b.y, c[2][1]);
            c[2][2] = fmaf(a.z, b.z, c[2][2]); c[2][3] = fmaf(a.z, b.w, c[2][3]);
            c[3][0] = fmaf(a.w, b.x, c[3][0]); c[3][1] = fmaf(a.w, b.y, c[3][1]);
            c[3][2] = fmaf(a.w, b.z, c[3][2]); c[3][3] = fmaf(a.w, b.w, c[3][3]);
        }
        __syncthreads();
    }

    #pragma unroll
    for (int i = 0; i < 4; i++) {
        int r = rbase + ty * 4 + i;
        if (r < NN) {
            float d = g_dis[r];
            float4 o = make_float4(c[i][0] * d, c[i][1] * d, c[i][2] * d, c[i][3] * d);
            *(float4*)(g_xws + (size_t)r * F2 + tx * 4) = o;
        }
    }
}

// ---------------- agg1: float4 gather, 2 edges/warp in flight ---------------
__global__ void k_agg1(const float* __restrict__ b1) {
    int lane = threadIdx.x & 31;
    int c4 = lane & 15;     // float4 chunk
    int half = lane >> 4;   // 0 or 1
    int n = blockIdx.x * 8 + (threadIdx.x >> 5);
    if (n >= NN) return;
    int beg = g_off[n], end = g_off[n + 1];
    const float4* xws4 = (const float4*)g_xws;  // 16 per row

    float4 acc = make_float4(0.f, 0.f, 0.f, 0.f);
    if (half == 1) acc = xws4[(size_t)n * 16 + c4];  // self-loop in half 1

    for (int base = beg; base < end; base += 32) {
        int cnt = min(32, end - base);
        int sl = (lane < cnt) ? g_csr[base + lane] : 0;
        int k = 0;
        for (; k + 1 < cnt; k += 2) {
            int s = __shfl_sync(0xffffffffu, sl, k + half);
            float4 v = xws4[(size_t)s * 16 + c4];
            acc.x += v.x; acc.y += v.y; acc.z += v.z; acc.w += v.w;
        }
        if (k < cnt) {
            int s = __shfl_sync(0xffffffffu, sl, k);
            if (half == 0) {
                float4 v = xws4[(size_t)s * 16 + c4];
                acc.x += v.x; acc.y += v.y; acc.z += v.z; acc.w += v.w;
            }
        }
    }
    // combine halves
    acc.x += __shfl_xor_sync(0xffffffffu, acc.x, 16);
    acc.y += __shfl_xor_sync(0xffffffffu, acc.y, 16);
    acc.z += __shfl_xor_sync(0xffffffffu, acc.z, 16);
    acc.w += __shfl_xor_sync(0xffffffffu, acc.w, 16);

    if (half == 0) {
        float d = g_dis[n];
        float4 bb = *(const float4*)(b1 + c4 * 4);
        float4 o = make_float4(fmaxf(d * acc.x + bb.x, 0.f),
                               fmaxf(d * acc.y + bb.y, 0.f),
                               fmaxf(d * acc.z + bb.z, 0.f),
                               fmaxf(d * acc.w + bb.w, 0.f));
        *(float4*)(g_h + (size_t)n * F2 + c4 * 4) = o;
    }
}

// ---------------- GEMM2: hw = (h @ W2) * dis (warp-shuffle) -----------------
__global__ void k_gemm2(const float* __restrict__ W) {
    __shared__ float sW[F2 * F3];
    int tid = threadIdx.x;
    for (int idx = tid; idx < F2 * F3; idx += blockDim.x) sW[idx] = W[idx];
    __syncthreads();

    int lane = tid & 31, warp = tid >> 5;
    int rbase = blockIdx.x * 32 + warp * 4;

    float xr[4][2];
    #pragma unroll
    for (int j = 0; j < 4; j++) {
        int r = min(rbase + j, NN - 1);
        xr[j][0] = g_h[(size_t)r * F2 + lane];
        xr[j][1] = g_h[(size_t)r * F2 + lane + 32];
    }

    float a0[4] = {0.f, 0.f, 0.f, 0.f}, a1[4] = {0.f, 0.f, 0.f, 0.f};
    int c2 = 32 + (lane & 7);
    #pragma unroll
    for (int k = 0; k < F2; k++) {
        float w0 = sW[k * F3 + lane];
        float w1 = sW[k * F3 + c2];
        #pragma unroll
        for (int j = 0; j < 4; j++) {
            float xk = __shfl_sync(0xffffffffu, xr[j][k >> 5], k & 31);
            a0[j] = fmaf(xk, w0, a0[j]);
            a1[j] = fmaf(xk, w1, a1[j]);
        }
    }

    #pragma unroll
    for (int j = 0; j < 4; j++) {
        int r = rbase + j;
        if (r < NN) {
            float d = g_dis[r];
            g_hwf[(size_t)r * F3 + lane] = a0[j] * d;
            if (lane < 8) g_hwf[(size_t)r * F3 + c2] = a1[j] * d;
        }
    }
}

// ---------------- agg2: reduce + self + bias + log-softmax ------------------
__global__ void k_agg2(const float* __restrict__ b2, float* __restrict__ out) {
    int lane = threadIdx.x & 31;
    int n = blockIdx.x * 8 + (threadIdx.x >> 5);
    if (n >= NN) return;
    bool act = lane < 20;
    const float2* hw2 = (const float2*)g_hwf;  // 20 per row
    int beg = g_off[n], end = g_off[n + 1];

    float2 accA = act ? hw2[(size_t)n * 20 + lane] : make_float2(0.f, 0.f);
    float2 accB = make_float2(0.f, 0.f);

    for (int base = beg; base < end; base += 32) {
        int cnt = min(32, end - base);
        int sl = (lane < cnt) ? g_csr[base + lane] : 0;
        int k = 0;
        for (; k + 1 < cnt; k += 2) {
            int s0 = __shfl_sync(0xffffffffu, sl, k);
            int s1 = __shfl_sync(0xffffffffu, sl, k + 1);
            if (act) {
                float2 v0 = hw2[(size_t)s0 * 20 + lane];
                float2 v1 = hw2[(size_t)s1 * 20 + lane];
                accA.x += v0.x; accA.y += v0.y;
                accB.x += v1.x; accB.y += v1.y;
            }
        }
        if (k < cnt) {
            int s0 = __shfl_sync(0xffffffffu, sl, k);
            if (act) {
                float2 v = hw2[(size_t)s0 * 20 + lane];
                accA.x += v.x; accA.y += v.y;
            }
        }
    }

    float d = g_dis[n];
    float zx = act ? d * (accA.x + accB.x) + b2[2 * lane]     : -3.4e38f;
    float zy = act ? d * (accA.y + accB.y) + b2[2 * lane + 1] : -3.4e38f;

    float m = fmaxf(zx, zy);
    #pragma unroll
    for (int o = 16; o; o >>= 1) m = fmaxf(m, __shfl_xor_sync(0xffffffffu, m, o));
    float s = act ? (expf(zx - m) + expf(zy - m)) : 0.f;
    #pragma unroll
    for (int o = 16; o; o >>= 1) s += __shfl_xor_sync(0xffffffffu, s, o);
    float lse = m + logf(s);

    if (act) {
        out[(size_t)n * F3 + 2 * lane]     = zx - lse;
        out[(size_t)n * F3 + 2 * lane + 1] = zy - lse;
    }
}

// ---------------- launcher --------------------------------------------------
extern "C" void kernel_launch(void* const* d_in, const int* in_sizes, int n_in,
                              void* d_out, int out_size) {
    const float* x  = (const float*)d_in[0];
    const void*  ei = d_in[1];
    const float* W1 = (const float*)d_in[2];
    const float* b1 = (const float*)d_in[3];
    const float* W2 = (const float*)d_in[4];
    const float* b2 = (const float*)d_in[5];
    float* out = (float*)d_out;

    int E = in_sizes[1] / 2;
    int eb = (E + 255) / 256;

    // lazy one-time stream/event setup (host objects, no device memory)
    static cudaStream_t s2 = 0;
    static cudaEvent_t evA = 0, evB = 0;
    if (!s2) {
        cudaStreamCreateWithFlags(&s2, cudaStreamNonBlocking);
        cudaEventCreateWithFlags(&evA, cudaEventDisableTiming);
        cudaEventCreateWithFlags(&evB, cudaEventDisableTiming);
    }

    k_init<<<NB, 256>>>((const int*)ei);
    k_deg<<<eb, 256>>>(ei, E);
    k_dis_scan1<<<NB, 256>>>();

    // fork: gemm1 (needs only x, W1, dis) overlaps the CSR build
    cudaEventRecord(evA, 0);
    cudaStreamWaitEvent(s2, evA, 0);
    k_gemm1<<<(NN + 63) / 64, 256, 0, s2>>>(x, W1);
    cudaEventRecord(evB, s2);

    k_scan2<<<1, 512>>>();
    k_scan3<<<(NN + 256) / 256, 256>>>();
    k_fill<<<eb, 256>>>(ei, E);

    cudaStreamWaitEvent(0, evB, 0);  // join before agg1

    k_agg1<<<(NN + 7) / 8, 256>>>(b1);
    k_gemm2<<<(NN + 31) / 32, 256>>>(W2);
    k_agg2<<<(NN + 7) / 8, 256>>>(b2, out);
}

// round 7
// speedup vs baseline: 1.8375x; 1.1314x over previous
#include <cuda_runtime.h>

#define NN 100000
#define F1 128
#define F2 64
#define F3 40
#define EMAX 1700000
#define NB 391  // ceil(NN/256)

// ---------------- scratch ---------------------------------------------------
__device__ int   g_deg[NN];
__device__ float g_dis[NN];
__device__ int   g_off[NN + 1];
__device__ int   g_cur[NN];
__device__ int   g_bsum[512];
__device__ int   g_csr[EMAX];
__device__ __align__(16) float g_xws[NN * F2];  // (x@W1)*dis, natural [r][64]
__device__ __align__(16) float g_h[NN * F2];    // relu out, natural [r][64]
__device__ __align__(16) float g_hwf[NN * F3];  // (h@W2)*dis, natural [r][40]
__device__ int g_is64;

// ---------------- edge index fetch (dtype-agnostic) -------------------------
__device__ __forceinline__ int edge_idx(const void* ei, long long E,
                                        long long e, int which) {
    if (g_is64) return (int)((const long long*)ei)[(long long)which * E + e];
    return ((const int*)ei)[(long long)which * E + e];
}

// ---------------- init: dtype probe + zero degree ---------------------------
__global__ void k_init(const int* __restrict__ ei) {
    int i = blockIdx.x * blockDim.x + threadIdx.x;
    if (i < NN) g_deg[i] = 0;
    if (i == 0) {
        int ones = 0;
        for (int j = 0; j < 256; j++) ones |= ei[2 * j + 1];
        g_is64 = (ones == 0) ? 1 : 0;
    }
}

__global__ void k_deg(const void* __restrict__ ei, int E) {
    int i = blockIdx.x * blockDim.x + threadIdx.x;
    if (i >= E) return;
    int d = edge_idx(ei, E, i, 1);
    if ((unsigned)d < NN) atomicAdd(&g_deg[d], 1);
}

// ---------------- dis + scan step 1 -----------------------------------------
__global__ void k_dis_scan1() {
    __shared__ int wsum[8];
    int i = blockIdx.x * 256 + threadIdx.x;
    int lane = threadIdx.x & 31, w = threadIdx.x >> 5;
    int deg = (i < NN) ? g_deg[i] : 0;
    if (i < NN) g_dis[i] = rsqrtf((float)(deg + 1));
    int incl = deg;
    #pragma unroll
    for (int o = 1; o < 32; o <<= 1) {
        int t = __shfl_up_sync(0xffffffffu, incl, o);
        if (lane >= o) incl += t;
    }
    if (lane == 31) wsum[w] = incl;
    __syncthreads();
    if (w == 0) {
        int s = (lane < 8) ? wsum[lane] : 0;
        #pragma unroll
        for (int o = 1; o < 8; o <<= 1) {
            int t = __shfl_up_sync(0xffffffffu, s, o);
            if (lane >= o) s += t;
        }
        if (lane < 8) wsum[lane] = s;
    }
    __syncthreads();
    if (w > 0) incl += wsum[w - 1];
    if (i < NN) g_off[i + 1] = incl;
    if (threadIdx.x == 255) g_bsum[blockIdx.x] = incl;
}

__global__ void k_scan2() {
    __shared__ int s[512];
    int t = threadIdx.x;
    s[t] = (t < NB) ? g_bsum[t] : 0;
    __syncthreads();
    for (int o = 1; o < 512; o <<= 1) {
        int v = (t >= o) ? s[t - o] : 0;
        __syncthreads();
        s[t] += v;
        __syncthreads();
    }
    if (t < NB) g_bsum[t] = (t > 0) ? s[t - 1] : 0;
}

__global__ void k_scan3() {
    int j = blockIdx.x * blockDim.x + threadIdx.x;
    if (j > NN) return;
    int v = (j == 0) ? 0 : g_off[j] + g_bsum[(j - 1) >> 8];
    g_off[j] = v;
    if (j < NN) g_cur[j] = v;
}

__global__ void k_fill(const void* __restrict__ ei, int E) {
    int e = blockIdx.x * blockDim.x + threadIdx.x;
    if (e >= E) return;
    int s = edge_idx(ei, E, e, 0);
    int d = edge_idx(ei, E, e, 1);
    if ((unsigned)s >= NN || (unsigned)d >= NN) return;
    int pos = atomicAdd(&g_cur[d], 1);
    if (pos < EMAX) g_csr[pos] = s;
}

// ---------------- GEMM1: 128x64 block, 8x4 micro-tile, 256 thr --------------
__global__ void k_gemm1(const float* __restrict__ X, const float* __restrict__ W) {
    __shared__ float Xs[16][128];  // [k][row]
    __shared__ float Ws[16][64];   // [k][col]
    int tid = threadIdx.x;
    int rbase = blockIdx.x * 128;
    int m0 = (tid >> 4) * 8;       // 0..120
    int n0 = (tid & 15) * 4;       // 0..60

    float c[8][4] = {};

    #pragma unroll 1
    for (int kc = 0; kc < F1; kc += 16) {
        // load X tile (512 float4, 2 per thread), store transposed
        #pragma unroll
        for (int it = 0; it < 2; it++) {
            int idx = tid + it * 256;
            int row = idx >> 2, q = idx & 3;
            int rr = min(rbase + row, NN - 1);
            float4 v = *(const float4*)(X + (size_t)rr * F1 + kc + q * 4);
            Xs[q * 4 + 0][row] = v.x;
            Xs[q * 4 + 1][row] = v.y;
            Xs[q * 4 + 2][row] = v.z;
            Xs[q * 4 + 3][row] = v.w;
        }
        {   // load W tile (256 float4, 1 per thread)
            int k = tid >> 4, c4 = tid & 15;
            float4 v = *(const float4*)(W + (size_t)(kc + k) * F2 + c4 * 4);
            *(float4*)&Ws[k][c4 * 4] = v;
        }
        __syncthreads();
        #pragma unroll
        for (int k = 0; k < 16; k++) {
            float4 a0 = *(float4*)&Xs[k][m0];
            float4 a1 = *(float4*)&Xs[k][m0 + 4];
            float4 b  = *(float4*)&Ws[k][n0];
            float av[8] = {a0.x, a0.y, a0.z, a0.w, a1.x, a1.y, a1.z, a1.w};
            #pragma unroll
            for (int i = 0; i < 8; i++) {
                c[i][0] = fmaf(av[i], b.x, c[i][0]);
                c[i][1] = fmaf(av[i], b.y, c[i][1]);
                c[i][2] = fmaf(av[i], b.z, c[i][2]);
                c[i][3] = fmaf(av[i], b.w, c[i][3]);
            }
        }
        __syncthreads();
    }

    #pragma unroll
    for (int i = 0; i < 8; i++) {
        int r = rbase + m0 + i;
        if (r < NN) {
            float d = g_dis[r];
            float4 o = make_float4(c[i][0] * d, c[i][1] * d, c[i][2] * d, c[i][3] * d);
            *(float4*)(g_xws + (size_t)r * F2 + n0) = o;
        }
    }
}

// ---------------- agg1: float4 gather, 2 edges/warp in flight ---------------
__global__ void k_agg1(const float* __restrict__ b1) {
    int lane = threadIdx.x & 31;
    int c4 = lane & 15;     // float4 chunk
    int half = lane >> 4;   // 0 or 1
    int n = blockIdx.x * 8 + (threadIdx.x >> 5);
    if (n >= NN) return;
    int beg = g_off[n], end = g_off[n + 1];
    const float4* xws4 = (const float4*)g_xws;  // 16 per row

    float4 acc = make_float4(0.f, 0.f, 0.f, 0.f);
    if (half == 1) acc = xws4[(size_t)n * 16 + c4];  // self-loop in half 1

    for (int base = beg; base < end; base += 32) {
        int cnt = min(32, end - base);
        int sl = (lane < cnt) ? g_csr[base + lane] : 0;
        int k = 0;
        for (; k + 1 < cnt; k += 2) {
            int s = __shfl_sync(0xffffffffu, sl, k + half);
            float4 v = xws4[(size_t)s * 16 + c4];
            acc.x += v.x; acc.y += v.y; acc.z += v.z; acc.w += v.w;
        }
        if (k < cnt) {
            int s = __shfl_sync(0xffffffffu, sl, k);
            if (half == 0) {
                float4 v = xws4[(size_t)s * 16 + c4];
                acc.x += v.x; acc.y += v.y; acc.z += v.z; acc.w += v.w;
            }
        }
    }
    acc.x += __shfl_xor_sync(0xffffffffu, acc.x, 16);
    acc.y += __shfl_xor_sync(0xffffffffu, acc.y, 16);
    acc.z += __shfl_xor_sync(0xffffffffu, acc.z, 16);
    acc.w += __shfl_xor_sync(0xffffffffu, acc.w, 16);

    if (half == 0) {
        float d = g_dis[n];
        float4 bb = *(const float4*)(b1 + c4 * 4);
        float4 o = make_float4(fmaxf(d * acc.x + bb.x, 0.f),
                               fmaxf(d * acc.y + bb.y, 0.f),
                               fmaxf(d * acc.z + bb.z, 0.f),
                               fmaxf(d * acc.w + bb.w, 0.f));
        *(float4*)(g_h + (size_t)n * F2 + c4 * 4) = o;
    }
}

// ---------------- GEMM2: 128x40 block, 8x4 micro-tile, 160 thr --------------
__global__ void k_gemm2(const float* __restrict__ W) {
    __shared__ float Xs[16][128];  // [k][row]
    __shared__ float Ws[16][40];   // [k][col]
    int tid = threadIdx.x;
    int rbase = blockIdx.x * 128;
    int m0 = (tid / 10) * 8;       // 0..120
    int n0 = (tid % 10) * 4;       // 0..36

    float c[8][4] = {};

    #pragma unroll 1
    for (int kc = 0; kc < F2; kc += 16) {
        for (int idx = tid; idx < 512; idx += 160) {
            int row = idx >> 2, q = idx & 3;
            int rr = min(rbase + row, NN - 1);
            float4 v = *(const float4*)(g_h + (size_t)rr * F2 + kc + q * 4);
            Xs[q * 4 + 0][row] = v.x;
            Xs[q * 4 + 1][row] = v.y;
            Xs[q * 4 + 2][row] = v.z;
            Xs[q * 4 + 3][row] = v.w;
        }
        {   // 160 float4 = 16k x 10c4, 1 per thread
            int k = tid / 10, c4 = tid % 10;
            float4 v = *(const float4*)(W + (size_t)(kc + k) * F3 + c4 * 4);
            *(float4*)&Ws[k][c4 * 4] = v;
        }
        __syncthreads();
        #pragma unroll
        for (int k = 0; k < 16; k++) {
            float4 a0 = *(float4*)&Xs[k][m0];
            float4 a1 = *(float4*)&Xs[k][m0 + 4];
            float4 b  = *(float4*)&Ws[k][n0];
            float av[8] = {a0.x, a0.y, a0.z, a0.w, a1.x, a1.y, a1.z, a1.w};
            #pragma unroll
            for (int i = 0; i < 8; i++) {
                c[i][0] = fmaf(av[i], b.x, c[i][0]);
                c[i][1] = fmaf(av[i], b.y, c[i][1]);
                c[i][2] = fmaf(av[i], b.z, c[i][2]);
                c[i][3] = fmaf(av[i], b.w, c[i][3]);
            }
        }
        __syncthreads();
    }

    #pragma unroll
    for (int i = 0; i < 8; i++) {
        int r = rbase + m0 + i;
        if (r < NN) {
            float d = g_dis[r];
            float4 o = make_float4(c[i][0] * d, c[i][1] * d, c[i][2] * d, c[i][3] * d);
            *(float4*)(g_hwf + (size_t)r * F3 + n0) = o;
        }
    }
}

// ---------------- agg2: reduce + self + bias + log-softmax ------------------
__global__ void k_agg2(const float* __restrict__ b2, float* __restrict__ out) {
    int lane = threadIdx.x & 31;
    int n = blockIdx.x * 8 + (threadIdx.x >> 5);
    if (n >= NN) return;
    bool act = lane < 20;
    const float2* hw2 = (const float2*)g_hwf;  // 20 per row
    int beg = g_off[n], end = g_off[n + 1];

    float2 accA = act ? hw2[(size_t)n * 20 + lane] : make_float2(0.f, 0.f);
    float2 accB = make_float2(0.f, 0.f);

    for (int base = beg; base < end; base += 32) {
        int cnt = min(32, end - base);
        int sl = (lane < cnt) ? g_csr[base + lane] : 0;
        int k = 0;
        for (; k + 1 < cnt; k += 2) {
            int s0 = __shfl_sync(0xffffffffu, sl, k);
            int s1 = __shfl_sync(0xffffffffu, sl, k + 1);
            if (act) {
                float2 v0 = hw2[(size_t)s0 * 20 + lane];
                float2 v1 = hw2[(size_t)s1 * 20 + lane];
                accA.x += v0.x; accA.y += v0.y;
                accB.x += v1.x; accB.y += v1.y;
            }
        }
        if (k < cnt) {
            int s0 = __shfl_sync(0xffffffffu, sl, k);
            if (act) {
                float2 v = hw2[(size_t)s0 * 20 + lane];
                accA.x += v.x; accA.y += v.y;
            }
        }
    }

    float d = g_dis[n];
    float zx = act ? d * (accA.x + accB.x) + b2[2 * lane]     : -3.4e38f;
    float zy = act ? d * (accA.y + accB.y) + b2[2 * lane + 1] : -3.4e38f;

    float m = fmaxf(zx, zy);
    #pragma unroll
    for (int o = 16; o; o >>= 1) m = fmaxf(m, __shfl_xor_sync(0xffffffffu, m, o));
    float s = act ? (expf(zx - m) + expf(zy - m)) : 0.f;
    #pragma unroll
    for (int o = 16; o; o >>= 1) s += __shfl_xor_sync(0xffffffffu, s, o);
    float lse = m + logf(s);

    if (act) {
        out[(size_t)n * F3 + 2 * lane]     = zx - lse;
        out[(size_t)n * F3 + 2 * lane + 1] = zy - lse;
    }
}

// ---------------- launcher --------------------------------------------------
extern "C" void kernel_launch(void* const* d_in, const int* in_sizes, int n_in,
                              void* d_out, int out_size) {
    const float* x  = (const float*)d_in[0];
    const void*  ei = d_in[1];
    const float* W1 = (const float*)d_in[2];
    const float* b1 = (const float*)d_in[3];
    const float* W2 = (const float*)d_in[4];
    const float* b2 = (const float*)d_in[5];
    float* out = (float*)d_out;

    int E = in_sizes[1] / 2;
    int eb = (E + 255) / 256;

    static cudaStream_t s2 = 0;
    static cudaEvent_t evA = 0, evB = 0;
    if (!s2) {
        cudaStreamCreateWithFlags(&s2, cudaStreamNonBlocking);
        cudaEventCreateWithFlags(&evA, cudaEventDisableTiming);
        cudaEventCreateWithFlags(&evB, cudaEventDisableTiming);
    }

    k_init<<<NB, 256>>>((const int*)ei);
    k_deg<<<eb, 256>>>(ei, E);
    k_dis_scan1<<<NB, 256>>>();

    // fork: gemm1 (needs only x, W1, dis) overlaps the CSR build
    cudaEventRecord(evA, 0);
    cudaStreamWaitEvent(s2, evA, 0);
    k_gemm1<<<(NN + 127) / 128, 256, 0, s2>>>(x, W1);
    cudaEventRecord(evB, s2);

    k_scan2<<<1, 512>>>();
    k_scan3<<<(NN + 256) / 256, 256>>>();
    k_fill<<<eb, 256>>>(ei, E);

    cudaStreamWaitEvent(0, evB, 0);  // join before agg1

    k_agg1<<<(NN + 7) / 8, 256>>>(b1);
    k_gemm2<<<(NN + 127) / 128, 160>>>(W2);
    k_agg2<<<(NN + 7) / 8, 256>>>(b2, out);
}